// round 5
// baseline (speedup 1.0000x reference)
#include <cuda_runtime.h>
#include <cstdint>

#define B_ROWS  131072
#define IN_DIM  1024
#define H_DIM   256
#define OUT_DIM 256
#define M_TILE  128
#define THREADS 512
#define KCH     16          // K-chunk
#define LDX     20          // xs row stride (words), 20 mod 32 = 4  -> conflict-free A frags
#define LDW     264         // ws row stride (words), 264 mod 32 = 8 -> conflict-free B frags
#define LDH     260         // hs row stride (words), 260 mod 32 = 4 -> conflict-free A frags

// ---- smem byte offsets ----
#define OFF_BIAS 0                       // 256 floats
#define OFF_ID   1024                    // 256 bytes
#define OFF_XS   1280                    // 2 x 128*LDX*4 = 2 x 10240
#define OFF_WS   (OFF_XS + 2*M_TILE*LDX*4)        // 21760, 2 x 16*LDW*4 = 2 x 16896
#define OFF_HS   (OFF_WS + 2*KCH*LDW*4)           // 55552, 128*LDH*4 = 133120
#define SMEM_TOTAL (OFF_HS + M_TILE*LDH*4)        // 188672

__device__ uint32_t g_W1c[IN_DIM * H_DIM];   // tf32 bits, original [k][n] layout
__device__ uint32_t g_W2c[H_DIM * H_DIM];
__device__ uint32_t g_Woc[H_DIM * OUT_DIM];

__device__ __forceinline__ unsigned f2tf(float f) {
    unsigned u; asm("cvt.rna.tf32.f32 %0, %1;" : "=r"(u) : "f"(f)); return u;
}
__device__ __forceinline__ uint32_t smem_u32(const void* p) {
    uint32_t a;
    asm("{ .reg .u64 t; cvta.to.shared.u64 t, %1; cvt.u32.u64 %0, t; }" : "=r"(a) : "l"(p));
    return a;
}
__device__ __forceinline__ void cp16(uint32_t dst, const void* src) {
    asm volatile("cp.async.cg.shared.global [%0], [%1], 16;" :: "r"(dst), "l"(src) : "memory");
}
#define CP_COMMIT() asm volatile("cp.async.commit_group;" ::: "memory")
#define CP_WAIT1()  asm volatile("cp.async.wait_group 1;" ::: "memory")

__device__ __forceinline__ void mma8(float* c, const unsigned* a, unsigned b0, unsigned b1) {
    asm volatile(
        "mma.sync.aligned.m16n8k8.row.col.f32.tf32.tf32.f32 "
        "{%0,%1,%2,%3}, {%4,%5,%6,%7}, {%8,%9}, {%0,%1,%2,%3};"
        : "+f"(c[0]), "+f"(c[1]), "+f"(c[2]), "+f"(c[3])
        : "r"(a[0]), "r"(a[1]), "r"(a[2]), "r"(a[3]), "r"(b0), "r"(b1));
}
__device__ __forceinline__ float apply_act(float z, int id) {
    if (id == 0) return fmaxf(z, 0.0f);
    if (id == 1) return tanhf(z);
    if (id == 2) return 0.5f * z * (1.0f + erff(z * 0.7071067811865475f));
    return 1.0f / (1.0f + __expf(-z));
}

// pre-pass: elementwise fp32 -> tf32(rna) bits, layout preserved
__global__ void convert_w(const float* __restrict__ W1, const float* __restrict__ W2,
                          const float* __restrict__ Wo) {
    int idx = blockIdx.x * 256 + threadIdx.x;
    if (idx < 262144)            g_W1c[idx] = f2tf(W1[idx]);
    else if (idx < 327680)       g_W2c[idx - 262144] = f2tf(W2[idx - 262144]);
    else if (idx < 393216)       g_Woc[idx - 327680] = f2tf(Wo[idx - 327680]);
}

extern __shared__ unsigned char smem_raw[];

__global__ void __launch_bounds__(THREADS, 1) het_mlp_v5(
    const float* __restrict__ x,
    const float* __restrict__ b1, const float* __restrict__ b2, const float* __restrict__ bo,
    const int* __restrict__ act1, const int* __restrict__ act2,
    float* __restrict__ out)
{
    const int t    = threadIdx.x;
    const int lane = t & 31;
    const int wid  = t >> 5;          // 0..15
    const int g    = lane >> 2;       // 0..7
    const int tg   = lane & 3;        // 0..3
    const int arow = (wid & 3) * 32;  // 4 warp-groups along M
    const int wcol = (wid >> 2) * 64; // 4 warp-groups along N
    const int row0 = blockIdx.x * M_TILE;
    const uint32_t sm = smem_u32(smem_raw);

    float*          bias_s = (float*)(smem_raw + OFF_BIAS);
    unsigned char*  id_s   = smem_raw + OFF_ID;
    uint32_t*       xs     = (uint32_t*)(smem_raw + OFF_XS);   // [2][128][LDX]
    uint32_t*       ws     = (uint32_t*)(smem_raw + OFF_WS);   // [2][16][LDW]
    uint32_t*       hs     = (uint32_t*)(smem_raw + OFF_HS);   // [128][LDH]

    float c[2][8][4];

    // ---- fill helpers ----
    const int xr_r  = t >> 2;          // x fill: row 0..127
    const int xr_c4 = t & 3;           // float4 index 0..3 within 16-k chunk
    const int wf_r  = t >> 5;          // W fill: row 0..15
    const int wf_s0 = (t & 31) * 2;    // 16B-seg pair 0..62

    auto fill_w_async = [&](int s, const uint32_t* Wc, int kc) {
        uint32_t dst = sm + OFF_WS + s * (KCH * LDW * 4) + wf_r * (LDW * 4) + wf_s0 * 16;
        const uint32_t* src = Wc + (kc * KCH + wf_r) * 256 + wf_s0 * 4;
        cp16(dst, src);
        cp16(dst + 16, src + 4);
    };
    auto ldg_x = [&](int kc) -> float4 {
        return *(const float4*)(x + (size_t)(row0 + xr_r) * IN_DIM + kc * KCH + xr_c4 * 4);
    };
    auto sts_x = [&](int s, float4 v) {
        uint32_t* d = xs + s * (M_TILE * LDX) + xr_r * LDX + xr_c4 * 4;
        d[0] = f2tf(v.x); d[1] = f2tf(v.y); d[2] = f2tf(v.z); d[3] = f2tf(v.w);
    };

    // ---- compute one K=16 chunk: C += A[128xK] * W[Kx256] ----
    auto compute_chunk = [&](const uint32_t* Abase, int lda, const uint32_t* Wbase) {
        #pragma unroll
        for (int ks = 0; ks < 2; ks++) {
            int k0 = ks * 8;
            unsigned a[2][4];
            #pragma unroll
            for (int rb = 0; rb < 2; rb++) {
                const uint32_t* ap = Abase + (arow + rb * 16 + g) * lda + k0 + tg;
                a[rb][0] = ap[0];
                a[rb][1] = ap[8 * lda];
                a[rb][2] = ap[4];
                a[rb][3] = ap[8 * lda + 4];
            }
            const uint32_t* w0 = Wbase + (k0 + tg) * LDW + wcol + g;
            const uint32_t* w1 = w0 + 4 * LDW;
            #pragma unroll
            for (int cb = 0; cb < 8; cb++) {
                unsigned b0 = w0[cb * 8], b1 = w1[cb * 8];
                mma8(c[0][cb], a[0], b0, b1);
                mma8(c[1][cb], a[1], b0, b1);
            }
        }
    };
    auto zero_c = [&]() {
        #pragma unroll
        for (int rb = 0; rb < 2; rb++)
            #pragma unroll
            for (int cb = 0; cb < 8; cb++)
                c[rb][cb][0] = c[rb][cb][1] = c[rb][cb][2] = c[rb][cb][3] = 0.0f;
    };
    // epilogue -> hs (bias + per-column activation, stored tf32)
    auto epilogue_h = [&]() {
        #pragma unroll
        for (int cb = 0; cb < 8; cb++) {
            int col = wcol + cb * 8 + 2 * tg;
            float bb0 = bias_s[col], bb1 = bias_s[col + 1];
            int   id0 = id_s[col],   id1 = id_s[col + 1];
            #pragma unroll
            for (int rb = 0; rb < 2; rb++) {
                #pragma unroll
                for (int h = 0; h < 2; h++) {
                    int row = arow + rb * 16 + g + 8 * h;
                    uint2 v;
                    v.x = f2tf(apply_act(c[rb][cb][2 * h]     + bb0, id0));
                    v.y = f2tf(apply_act(c[rb][cb][2 * h + 1] + bb1, id1));
                    *(uint2*)(hs + row * LDH + col) = v;
                }
            }
        }
    };

    // ================= Layer 1: K=1024, 64 chunks =================
    zero_c();
    if (t < 256) { bias_s[t] = b1[t]; id_s[t] = (unsigned char)act1[t]; }
    // prologue
    sts_x(0, ldg_x(0));
    sts_x(1, ldg_x(1));
    fill_w_async(0, g_W1c, 0); CP_COMMIT();
    fill_w_async(1, g_W1c, 1); CP_COMMIT();
    float4 xr_a = ldg_x(2);
    float4 xr_b = ldg_x(3);
    CP_WAIT1();
    __syncthreads();

    for (int kc = 0; kc < 64; kc++) {
        int s = kc & 1;
        compute_chunk(xs + s * (M_TILE * LDX), LDX, ws + s * (KCH * LDW));
        __syncthreads();                       // all warps done with buffer s
        if (kc + 2 < 64) {
            sts_x(s, xr_a);                    // chunk kc+2 -> xs[s]
            xr_a = xr_b;
            if (kc + 4 < 64) xr_b = ldg_x(kc + 4);
            fill_w_async(s, g_W1c, kc + 2);
        }
        CP_COMMIT();                           // one group per iter (may be empty)
        CP_WAIT1();                            // chunk kc+1 W ready
        __syncthreads();                       // visibility of xs/ws for next iter
    }
    epilogue_h();
    __syncthreads();

    // ================= Layer 2: K=256, 16 chunks (A = hs) =================
    zero_c();
    if (t < 256) { bias_s[t] = b2[t]; id_s[t] = (unsigned char)act2[t]; }
    fill_w_async(0, g_W2c, 0); CP_COMMIT();
    fill_w_async(1, g_W2c, 1); CP_COMMIT();
    CP_WAIT1();
    __syncthreads();
    for (int kc = 0; kc < 16; kc++) {
        int s = kc & 1;
        compute_chunk(hs + kc * KCH, LDH, ws + s * (KCH * LDW));
        __syncthreads();
        if (kc + 2 < 16) fill_w_async(s, g_W2c, kc + 2);
        CP_COMMIT();
        CP_WAIT1();
        __syncthreads();
    }
    epilogue_h();       // overwrites hs with h2 (all reads finished: sync in last iter)
    __syncthreads();

    // ================= Layer 3: K=256, 16 chunks =================
    zero_c();
    if (t < 256) bias_s[t] = bo[t];
    fill_w_async(0, g_Woc, 0); CP_COMMIT();
    fill_w_async(1, g_Woc, 1); CP_COMMIT();
    CP_WAIT1();
    __syncthreads();
    for (int kc = 0; kc < 16; kc++) {
        int s = kc & 1;
        compute_chunk(hs + kc * KCH, LDH, ws + s * (KCH * LDW));
        __syncthreads();
        if (kc + 2 < 16) fill_w_async(s, g_Woc, kc + 2);
        CP_COMMIT();
        CP_WAIT1();
        __syncthreads();
    }
    // epilogue -> gmem
    #pragma unroll
    for (int cb = 0; cb < 8; cb++) {
        int col = wcol + cb * 8 + 2 * tg;
        float bb0 = bias_s[col], bb1 = bias_s[col + 1];
        #pragma unroll
        for (int rb = 0; rb < 2; rb++) {
            #pragma unroll
            for (int h = 0; h < 2; h++) {
                int row = row0 + arow + rb * 16 + g + 8 * h;
                float2 v = make_float2(c[rb][cb][2 * h] + bb0, c[rb][cb][2 * h + 1] + bb1);
                *(float2*)(out + (size_t)row * OUT_DIM + col) = v;
            }
        }
    }
}

extern "C" void kernel_launch(void* const* d_in, const int* in_sizes, int n_in,
                              void* d_out, int out_size) {
    (void)in_sizes; (void)n_in; (void)out_size;
    const float* x  = (const float*)d_in[0];
    const float* W1 = (const float*)d_in[1];
    const float* b1 = (const float*)d_in[2];
    const float* W2 = (const float*)d_in[3];
    const float* b2 = (const float*)d_in[4];
    const float* Wo = (const float*)d_in[5];
    const float* bo = (const float*)d_in[6];
    const int*   a1 = (const int*)d_in[7];
    const int*   a2 = (const int*)d_in[8];

    convert_w<<<1536, 256>>>(W1, W2, Wo);

    cudaFuncSetAttribute(het_mlp_v5, cudaFuncAttributeMaxDynamicSharedMemorySize, SMEM_TOTAL);
    het_mlp_v5<<<B_ROWS / M_TILE, THREADS, SMEM_TOTAL>>>(
        x, b1, b2, bo, a1, a2, (float*)d_out);
}

// round 6
// speedup vs baseline: 1.6782x; 1.6782x over previous
#include <cuda_runtime.h>
#include <cuda_fp16.h>
#include <cstdint>

#define B_ROWS  131072
#define IN_DIM  1024
#define H_DIM   256
#define OUT_DIM 256
#define M_TILE  128
#define THREADS 512
#define KCH     32            // K elems per chunk
#define NSTG    3

// fp16 smem pitches (elements). Byte pitches: 80, 528, 528 -> lane rows distinct mod 128.
#define LDXH 40
#define LDWH 264
#define LDHH 264

#define XS_STAGE (M_TILE * LDXH * 2)      // 10240 B
#define WS_STAGE (KCH * LDWH * 2)         // 16896 B

#define OFF_BIAS 0
#define OFF_ID   1024
#define OFF_XS   1280
#define OFF_WS   (OFF_XS + NSTG * XS_STAGE)          // 32000
#define OFF_HS   (OFF_WS + NSTG * WS_STAGE)          // 82688
#define SMEM_TOTAL (OFF_HS + M_TILE * LDHH * 2)      // 150272

__device__ __half g_W1h[IN_DIM * H_DIM];   // [k][n], layout preserved
__device__ __half g_W2h[H_DIM * H_DIM];
__device__ __half g_Woh[H_DIM * OUT_DIM];

__device__ __forceinline__ uint32_t smem_u32(const void* p) {
    uint32_t a;
    asm("{ .reg .u64 t; cvta.to.shared.u64 t, %1; cvt.u32.u64 %0, t; }" : "=r"(a) : "l"(p));
    return a;
}
__device__ __forceinline__ void cp16(uint32_t dst, const void* src) {
    asm volatile("cp.async.cg.shared.global [%0], [%1], 16;" :: "r"(dst), "l"(src) : "memory");
}
#define CP_COMMIT() asm volatile("cp.async.commit_group;" ::: "memory")
#define CP_WAIT1()  asm volatile("cp.async.wait_group 1;" ::: "memory")

__device__ __forceinline__ void ldsm4(uint32_t* r, uint32_t a) {
    asm volatile("ldmatrix.sync.aligned.m8n8.x4.shared.b16 {%0,%1,%2,%3}, [%4];"
                 : "=r"(r[0]), "=r"(r[1]), "=r"(r[2]), "=r"(r[3]) : "r"(a));
}
__device__ __forceinline__ void ldsm4t(uint32_t* r, uint32_t a) {
    asm volatile("ldmatrix.sync.aligned.m8n8.x4.trans.shared.b16 {%0,%1,%2,%3}, [%4];"
                 : "=r"(r[0]), "=r"(r[1]), "=r"(r[2]), "=r"(r[3]) : "r"(a));
}
__device__ __forceinline__ void mma16(float* c, const uint32_t* a, uint32_t b0, uint32_t b1) {
    asm volatile(
        "mma.sync.aligned.m16n8k16.row.col.f32.f16.f16.f32 "
        "{%0,%1,%2,%3}, {%4,%5,%6,%7}, {%8,%9}, {%0,%1,%2,%3};"
        : "+f"(c[0]), "+f"(c[1]), "+f"(c[2]), "+f"(c[3])
        : "r"(a[0]), "r"(a[1]), "r"(a[2]), "r"(a[3]), "r"(b0), "r"(b1));
}
__device__ __forceinline__ uint32_t pack2(float lo, float hi) {
    __half2 h = __floats2half2_rn(lo, hi);
    return *(uint32_t*)&h;
}
__device__ __forceinline__ float apply_act(float z, int id) {
    if (id == 0) return fmaxf(z, 0.0f);
    if (id == 1) return tanhf(z);
    if (id == 2) return 0.5f * z * (1.0f + erff(z * 0.7071067811865475f));
    return 1.0f / (1.0f + __expf(-z));
}

// pre-pass: fp32 -> fp16 (rn), layout preserved
__global__ void convert_w(const float* __restrict__ W1, const float* __restrict__ W2,
                          const float* __restrict__ Wo) {
    int idx = blockIdx.x * 256 + threadIdx.x;
    if (idx < 262144)       g_W1h[idx]          = __float2half_rn(W1[idx]);
    else if (idx < 327680)  g_W2h[idx - 262144] = __float2half_rn(W2[idx - 262144]);
    else if (idx < 393216)  g_Woh[idx - 327680] = __float2half_rn(Wo[idx - 327680]);
}

extern __shared__ unsigned char smem_raw[];

__global__ void __launch_bounds__(THREADS, 1) het_mlp_v6(
    const float* __restrict__ x,
    const float* __restrict__ b1, const float* __restrict__ b2, const float* __restrict__ bo,
    const int* __restrict__ act1, const int* __restrict__ act2,
    float* __restrict__ out)
{
    const int t    = threadIdx.x;
    const int lane = t & 31;
    const int wid  = t >> 5;            // 0..15
    const int g    = lane >> 2;
    const int tg   = lane & 3;
    const int arow = (wid & 3) * 32;    // 4 warps along M (32 rows each)
    const int wcol = (wid >> 2) * 64;   // 4 warps along N (64 cols each)
    const int row0 = blockIdx.x * M_TILE;
    const uint32_t sm = smem_u32(smem_raw);

    float*         bias_s = (float*)(smem_raw + OFF_BIAS);
    unsigned char* id_s   = smem_raw + OFF_ID;

    // ldmatrix lane offsets
    const uint32_t lrow = lane & 15, lseg = (lane >> 4) * 16;
    const uint32_t aoff_x = lrow * 80  + lseg;          // xs pitch 80B
    const uint32_t aoff_h = lrow * 528 + lseg;          // hs pitch 528B
    const uint32_t boff   = lrow * 528 + lseg;          // ws pitch 528B

    float c[2][8][4];
    auto zero_c = [&]() {
        #pragma unroll
        for (int rb = 0; rb < 2; rb++)
            #pragma unroll
            for (int cb = 0; cb < 8; cb++)
                c[rb][cb][0] = c[rb][cb][1] = c[rb][cb][2] = c[rb][cb][3] = 0.0f;
    };

    // ---- compute one K=32 chunk ----
    auto compute_chunk = [&](uint32_t abase, uint32_t arst, uint32_t wbase) {
        #pragma unroll
        for (int kb = 0; kb < 2; kb++) {
            uint32_t a0[4], a1[4];
            ldsm4(a0, abase + kb * 32);
            ldsm4(a1, abase + 16 * arst + kb * 32);
            #pragma unroll
            for (int nb = 0; nb < 4; nb++) {
                uint32_t b[4];
                ldsm4t(b, wbase + kb * (16 * 528) + nb * 32);
                mma16(c[0][2 * nb],     a0, b[0], b[1]);
                mma16(c[0][2 * nb + 1], a0, b[2], b[3]);
                mma16(c[1][2 * nb],     a1, b[0], b[1]);
                mma16(c[1][2 * nb + 1], a1, b[2], b[3]);
            }
        }
    };

    // ---- fills ----
    const int wf_r   = t >> 4;          // 0..31 (k row)
    const int wf_seg = t & 15;          // 16B seg pair
    auto fill_w = [&](int s, const __half* Wh, int kc) {
        uint32_t dst = sm + OFF_WS + s * WS_STAGE + wf_r * 528 + wf_seg * 32;
        const __half* src = Wh + (size_t)(kc * KCH + wf_r) * 256 + wf_seg * 16;
        cp16(dst, src);
        cp16(dst + 16, src + 8);
    };
    const int xf_r  = t >> 2;           // 0..127 via idx
    auto ldg_x = [&](int kc, float4* r) {
        #pragma unroll
        for (int i = 0; i < 2; i++) {
            int idx = t + i * THREADS;  // 0..1023
            int row = idx >> 3, c4 = idx & 7;
            r[i] = *(const float4*)(x + (size_t)(row0 + row) * IN_DIM + kc * KCH + c4 * 4);
        }
    };
    auto sts_x = [&](int s, const float4* r) {
        #pragma unroll
        for (int i = 0; i < 2; i++) {
            int idx = t + i * THREADS;
            int row = idx >> 3, c4 = idx & 7;
            uint2 v;
            v.x = pack2(r[i].x, r[i].y);
            v.y = pack2(r[i].z, r[i].w);
            *(uint2*)(smem_raw + OFF_XS + s * XS_STAGE + row * 80 + c4 * 8) = v;
        }
    };
    // epilogue -> hs (bias + act, fp16)
    auto epilogue_h = [&]() {
        #pragma unroll
        for (int cb = 0; cb < 8; cb++) {
            int col = wcol + cb * 8 + 2 * tg;
            float bb0 = bias_s[col], bb1 = bias_s[col + 1];
            int   id0 = id_s[col],   id1 = id_s[col + 1];
            #pragma unroll
            for (int rb = 0; rb < 2; rb++) {
                #pragma unroll
                for (int h = 0; h < 2; h++) {
                    int row = arow + rb * 16 + g + 8 * h;
                    float a0 = apply_act(c[rb][cb][2 * h]     + bb0, id0);
                    float a1 = apply_act(c[rb][cb][2 * h + 1] + bb1, id1);
                    *(uint32_t*)(smem_raw + OFF_HS + row * 528 + col * 2) = pack2(a0, a1);
                }
            }
        }
    };

    // ================= Layer 1: 32 chunks of K=32 =================
    zero_c();
    if (t < 256) { bias_s[t] = b1[t]; id_s[t] = (unsigned char)act1[t]; }
    float4 xr[2];
    ldg_x(0, xr); sts_x(0, xr);
    ldg_x(1, xr); sts_x(1, xr);
    fill_w(0, g_W1h, 0); CP_COMMIT();
    fill_w(1, g_W1h, 1); CP_COMMIT();
    ldg_x(2, xr);

    for (int i = 0; i < 32; i++) {
        int s = i % NSTG;
        CP_WAIT1();
        __syncthreads();
        if (i + 2 < 32) {
            fill_w((i + 2) % NSTG, g_W1h, i + 2);
            sts_x((i + 2) % NSTG, xr);
            if (i + 3 < 32) ldg_x(i + 3, xr);
        }
        CP_COMMIT();
        compute_chunk(sm + OFF_XS + s * XS_STAGE + arow * 80 + aoff_x, 80,
                      sm + OFF_WS + s * WS_STAGE + wcol * 2 + boff);
    }
    epilogue_h();
    __syncthreads();

    // ================= Layer 2: 8 chunks of K=32 (A = hs) =================
    zero_c();
    if (t < 256) { bias_s[t] = b2[t]; id_s[t] = (unsigned char)act2[t]; }
    fill_w(0, g_W2h, 0); CP_COMMIT();
    fill_w(1, g_W2h, 1); CP_COMMIT();
    for (int i = 0; i < 8; i++) {
        int s = i % NSTG;
        CP_WAIT1();
        __syncthreads();
        if (i + 2 < 8) fill_w((i + 2) % NSTG, g_W2h, i + 2);
        CP_COMMIT();
        compute_chunk(sm + OFF_HS + arow * 528 + i * 64 + aoff_h, 528,
                      sm + OFF_WS + s * WS_STAGE + wcol * 2 + boff);
    }
    __syncthreads();          // all reads of hs done before overwrite
    epilogue_h();
    __syncthreads();

    // ================= Layer 3: 8 chunks of K=32 =================
    zero_c();
    if (t < 256) bias_s[t] = bo[t];
    fill_w(0, g_Woh, 0); CP_COMMIT();
    fill_w(1, g_Woh, 1); CP_COMMIT();
    for (int i = 0; i < 8; i++) {
        int s = i % NSTG;
        CP_WAIT1();
        __syncthreads();
        if (i + 2 < 8) fill_w((i + 2) % NSTG, g_Woh, i + 2);
        CP_COMMIT();
        compute_chunk(sm + OFF_HS + arow * 528 + i * 64 + aoff_h, 528,
                      sm + OFF_WS + s * WS_STAGE + wcol * 2 + boff);
    }
    // epilogue -> gmem (fp32)
    #pragma unroll
    for (int cb = 0; cb < 8; cb++) {
        int col = wcol + cb * 8 + 2 * tg;
        float bb0 = bias_s[col], bb1 = bias_s[col + 1];
        #pragma unroll
        for (int rb = 0; rb < 2; rb++) {
            #pragma unroll
            for (int h = 0; h < 2; h++) {
                int row = row0 + arow + rb * 16 + g + 8 * h;
                float2 v = make_float2(c[rb][cb][2 * h] + bb0, c[rb][cb][2 * h + 1] + bb1);
                *(float2*)(out + (size_t)row * OUT_DIM + col) = v;
            }
        }
    }
}

extern "C" void kernel_launch(void* const* d_in, const int* in_sizes, int n_in,
                              void* d_out, int out_size) {
    (void)in_sizes; (void)n_in; (void)out_size;
    const float* x  = (const float*)d_in[0];
    const float* W1 = (const float*)d_in[1];
    const float* b1 = (const float*)d_in[2];
    const float* W2 = (const float*)d_in[3];
    const float* b2 = (const float*)d_in[4];
    const float* Wo = (const float*)d_in[5];
    const float* bo = (const float*)d_in[6];
    const int*   a1 = (const int*)d_in[7];
    const int*   a2 = (const int*)d_in[8];

    convert_w<<<1536, 256>>>(W1, W2, Wo);

    cudaFuncSetAttribute(het_mlp_v6, cudaFuncAttributeMaxDynamicSharedMemorySize, SMEM_TOTAL);
    het_mlp_v6<<<B_ROWS / M_TILE, THREADS, SMEM_TOTAL>>>(
        x, b1, b2, bo, a1, a2, (float*)d_out);
}